// round 8
// baseline (speedup 1.0000x reference)
#include <cuda_runtime.h>
#include <cuda_bf16.h>
#include <cstdint>

// Focal BCE-with-logits, mean-reduced. Single fused kernel.
// cp.async per-thread 3-stage pipeline: decouples outstanding-load depth from
// the register file (smem as load-landing buffer, no CTA barriers needed).
// Math (2 MUFU + soft exp2):
//   nxl = -x*log2e ; t = 2^nxl = exp(-x) ; l = log2(1+t)
//   log2(p) = -l ; log2(1-p) = nxl - l = d
//   pos: loss = (ALPHA*ln2*l)      * 2^(G*d)
//   neg: loss = (-(1-ALPHA)*ln2*d) * 2^(G*(-l))

#define GRID_BLOCKS 888          // 148 SMs * 6 CTAs: single wave guaranteed
#define BLOCK_THREADS 256
#define STAGES 3

__device__ float        g_partials[GRID_BLOCKS];
__device__ unsigned int g_ticket;   // zero-init; last block resets each launch

__device__ __forceinline__ float fast_ex2(float x) {
    float r; asm("ex2.approx.ftz.f32 %0, %1;" : "=f"(r) : "f"(x)); return r;
}
__device__ __forceinline__ float fast_lg2(float x) {
    float r; asm("lg2.approx.ftz.f32 %0, %1;" : "=f"(r) : "f"(x)); return r;
}

// Software exp2 for u in ~[-2, 0.01]: round-bias trick + deg-4 poly + exponent insert.
__device__ __forceinline__ float soft_ex2(float u) {
    const float RND = 12582912.0f;             // 1.5 * 2^23
    float t2 = u + RND;
    float rn = t2 - RND;
    float f  = u - rn;                         // [-0.5, 0.5]
    int   sc_i = (__float_as_int(t2) + (127 - 0x400000)) << 23;  // bits of 2^n
    float z = fmaf(0.0096181f, f, 0.0555041f);
    z = fmaf(z, f, 0.2402265f);
    z = fmaf(z, f, 0.6931472f);
    z = fmaf(z, f, 1.0f);
    return z * __int_as_float(sc_i);
}

__device__ __forceinline__ float focal_elem(float x, int tg) {
    const float LOG2E = 1.4426950408889634f;
    const float LN2   = 0.6931471805599453f;
    const float GAMMA = 0.2f;
    const float C1 =  0.6f * LN2;   //  alpha * ln2
    const float C0 = -0.4f * LN2;   // -(1-alpha) * ln2
    float nxl = -x * LOG2E;
    float t   = fast_ex2(nxl);           // MUFU 1
    float l   = fast_lg2(1.0f + t);      // MUFU 2
    float d   = nxl - l;                 // log2(1-p)
    bool  pos = (tg == 1);
    float log2b = pos ? d : -l;
    float w     = pos ? (C1 * l) : (C0 * d);
    return soft_ex2(GAMMA * log2b) * w;  // no MUFU
}

// 16B global->shared async copy; pred=false => src_size 0 (pure zero-fill,
// no gmem access) with pointer clamped to a safe location.
__device__ __forceinline__ void cp16(void* sdst, const void* gsrc,
                                     const void* gsafe, bool pred) {
    unsigned int s = (unsigned int)__cvta_generic_to_shared(sdst);
    const void* g = pred ? gsrc : gsafe;
    int sz = pred ? 16 : 0;
    asm volatile("cp.async.cg.shared.global [%0], [%1], 16, %2;\n"
                 :: "r"(s), "l"(g), "r"(sz));
}
__device__ __forceinline__ void cp_commit() {
    asm volatile("cp.async.commit_group;\n" ::: "memory");
}
__device__ __forceinline__ void cp_wait2() {
    asm volatile("cp.async.wait_group 2;\n" ::: "memory");
}

__device__ __forceinline__ float block_reduce(float acc) {
    __shared__ float sw[BLOCK_THREADS / 32];
    int lane = threadIdx.x & 31;
    int wid  = threadIdx.x >> 5;
    #pragma unroll
    for (int off = 16; off > 0; off >>= 1)
        acc += __shfl_down_sync(0xffffffffu, acc, off);
    if (lane == 0) sw[wid] = acc;
    __syncthreads();
    float v = 0.0f;
    if (wid == 0) {
        v = (lane < (BLOCK_THREADS / 32)) ? sw[lane] : 0.0f;
        #pragma unroll
        for (int off = (BLOCK_THREADS / 64); off > 0; off >>= 1)
            v += __shfl_down_sync(0xffffffffu, v, off);
    }
    return v;  // valid in thread 0 only
}

__global__ void __launch_bounds__(BLOCK_THREADS, 6)
focal_pipe(const float* __restrict__ logits,
           const int*   __restrict__ target,
           float* __restrict__ out,
           long long n, float inv_n) {
    __shared__ float4 s_lg[STAGES][BLOCK_THREADS];
    __shared__ int4   s_tg[STAGES][BLOCK_THREADS];

    const long long n4     = n >> 2;     // quads; each stage = 1 quad/thread
    const long long stride = (long long)gridDim.x * blockDim.x;
    const long long q0     = (long long)blockIdx.x * blockDim.x + threadIdx.x;
    const int tid = threadIdx.x;
    const float4* lg4 = reinterpret_cast<const float4*>(logits);
    const int4*   tg4 = reinterpret_cast<const int4*>(target);

    // Prologue: stages 0 and 1 in flight.
    #pragma unroll
    for (int s = 0; s < STAGES - 1; s++) {
        long long q = q0 + (long long)s * stride;
        bool p = q < n4;
        cp16(&s_lg[s][tid], lg4 + q, lg4, p);
        cp16(&s_tg[s][tid], tg4 + q, tg4, p);
        cp_commit();
    }

    float acc = 0.0f;
    int buf = 0;
    #pragma unroll 1
    for (long long qk = q0; qk < n4; qk += stride) {
        // Prefetch stage k+2 into the buffer being vacated furthest ahead.
        long long qp = qk + 2 * stride;
        int bpre = buf + 2; if (bpre >= STAGES) bpre -= STAGES;
        bool p = qp < n4;
        cp16(&s_lg[bpre][tid], lg4 + qp, lg4, p);
        cp16(&s_tg[bpre][tid], tg4 + qp, tg4, p);
        cp_commit();
        cp_wait2();                       // stage k complete (<=2 groups pending)

        float4 x = s_lg[buf][tid];
        int4   t = s_tg[buf][tid];
        acc += focal_elem(x.x, t.x);
        acc += focal_elem(x.y, t.y);
        acc += focal_elem(x.z, t.z);
        acc += focal_elem(x.w, t.w);

        buf++; if (buf == STAGES) buf = 0;
    }

    // Scalar tail for n % 4 (empty for this problem's n, kept for generality).
    if (blockIdx.x == 0 && threadIdx.x == 0) {
        for (long long i = n4 << 2; i < n; i++)
            acc += focal_elem(logits[i], target[i]);
    }

    float v = block_reduce(acc);

    // ---- last-block final reduction (deterministic; no second kernel) ----
    __shared__ bool is_last;
    if (threadIdx.x == 0) {
        g_partials[blockIdx.x] = v;
        __threadfence();
        unsigned int t = atomicAdd(&g_ticket, 1u);
        is_last = (t == (unsigned int)(gridDim.x - 1));
    }
    __syncthreads();
    if (is_last) {
        float a = 0.0f;
        for (int i = threadIdx.x; i < (int)gridDim.x; i += blockDim.x)
            a += g_partials[i];
        float s = block_reduce(a);
        if (threadIdx.x == 0) {
            out[0]   = s * inv_n;
            g_ticket = 0;          // reset for next launch / graph replay
        }
    }
}

extern "C" void kernel_launch(void* const* d_in, const int* in_sizes, int n_in,
                              void* d_out, int out_size) {
    const float* logits = (const float*)d_in[0];
    const int*   target = (const int*)d_in[1];
    long long n = (long long)in_sizes[0];
    focal_pipe<<<GRID_BLOCKS, BLOCK_THREADS>>>(logits, target, (float*)d_out,
                                               n, 1.0f / (float)n);
}